// round 2
// baseline (speedup 1.0000x reference)
#include <cuda_runtime.h>

#define FULL 0xffffffffu
#define START_TAG 7
#define STOP_TAG 8
#define KDIM 9

// scratch (device globals: allocation-free rule)
__device__ float g_fwd[8192];
__device__ float g_gold[8192];

__device__ __forceinline__ float ex2(float x) {
    float y; asm("ex2.approx.f32 %0, %1;" : "=f"(y) : "f"(x)); return y;
}
__device__ __forceinline__ float lg2(float x) {
    float y; asm("lg2.approx.f32 %0, %1;" : "=f"(y) : "f"(x)); return y;
}

// ---------------------------------------------------------------------------
// Forward (log-partition) kernel: one warp per sentence, lanes 0..8 = states.
// Base-2 log domain. E2[j][i] = exp2(trans[j][i]*log2e) precomputed per lane.
// beta kept relative to running offset C; rebase by lane-0 beta every 8 steps.
// ---------------------------------------------------------------------------
__global__ void __launch_bounds__(128) crf_fwd_kernel(
    const float* __restrict__ feats, const float* __restrict__ trans,
    const int* __restrict__ lengths, int B, int T)
{
    const float L2E = 1.4426950408889634f;
    const float LN2 = 0.6931471805599453f;
    const float NINF = __int_as_float(0xff800000);

    int gwarp = blockIdx.x * (blockDim.x >> 5) + (threadIdx.x >> 5);
    int lane  = threadIdx.x & 31;
    if (gwarp >= B) return;
    const int b   = gwarp;
    const int len = lengths[b];
    const bool act = (lane < KDIM);
    const int  row = act ? lane : 0;

    // E2 row (outgoing into state j=lane). Row START is all exp2(-huge)=0.
    float E2[KDIM];
#pragma unroll
    for (int i = 0; i < KDIM; i++) {
        float tv = trans[row * KDIM + i];
        E2[i] = act ? ex2(tv * L2E) : 0.0f;
    }
    const float t2stop = act ? trans[STOP_TAG * KDIM + lane] * L2E : 0.0f;

    const float* frow = feats + (size_t)b * T * KDIM;

    // 8-deep prefetch ring for emissions (hides ~577cyc DRAM behind ~110cyc steps)
    float fb[8];
#pragma unroll
    for (int d = 0; d < 8; d++) {
        int tt = (d < T) ? d : (T - 1);
        fb[d] = act ? __ldg(frow + tt * KDIM + lane) : 0.0f;
    }

    float beta = (lane == START_TAG) ? 0.0f : NINF;
    float C = 0.0f;

    for (int t = 0; t < len; t++) {
        float f = fb[t & 7];
        int tn = t + 8; if (tn >= T) tn = T - 1;
        fb[t & 7] = act ? __ldg(frow + tn * KDIM + lane) : 0.0f;

        float e = ex2(beta);   // exp2(-inf) = 0 for dead states / idle lanes

        float v0 = __shfl_sync(FULL, e, 0);
        float v1 = __shfl_sync(FULL, e, 1);
        float v2 = __shfl_sync(FULL, e, 2);
        float v3 = __shfl_sync(FULL, e, 3);
        float v4 = __shfl_sync(FULL, e, 4);
        float v5 = __shfl_sync(FULL, e, 5);
        float v6 = __shfl_sync(FULL, e, 6);
        float v7 = __shfl_sync(FULL, e, 7);
        float v8 = __shfl_sync(FULL, e, 8);

        // 9-term dot, shallow tree for ILP
        float a0 = fmaf(E2[1], v1, E2[0] * v0);
        float a1 = fmaf(E2[3], v3, E2[2] * v2);
        float a2 = fmaf(E2[5], v5, E2[4] * v4);
        float a3 = fmaf(E2[7], v7, E2[6] * v6);
        float s  = (a0 + a1) + fmaf(E2[8], v8, a2 + a3);

        // beta_new = log2(sum) + feat*log2e   (offset folds into C at rebase)
        beta = fmaf(f, L2E, lg2(s));   // lg2(0) = -inf (START row / idle lanes)

        if ((t & 7) == 7) {
            float m = __shfl_sync(FULL, beta, 0);  // lane0 always finite
            beta -= m;
            C += m;
        }
    }

    // final: logZ = ln2 * ( C + log2 sum_j exp2(beta_j + trans[STOP,j]*l2e) )
    float v = act ? (beta + t2stop) : NINF;
    float mx = v;
#pragma unroll
    for (int k = 8; k; k >>= 1)
        mx = fmaxf(mx, __shfl_xor_sync(FULL, mx, k, 16));
    float p = ex2(v - mx);              // lanes 0..15; upper half garbage unused
    float sum = p;
#pragma unroll
    for (int k = 8; k; k >>= 1)
        sum += __shfl_xor_sync(FULL, sum, k, 16);
    if (lane == 0)
        g_fwd[b] = LN2 * (C + mx + lg2(sum));
}

// ---------------------------------------------------------------------------
// Gold-path score kernel: one warp per sentence, lanes stride over time.
// ---------------------------------------------------------------------------
__global__ void __launch_bounds__(128) crf_gold_kernel(
    const float* __restrict__ feats, const float* __restrict__ trans,
    const int* __restrict__ tags, const int* __restrict__ lengths,
    int B, int T)
{
    __shared__ float tr[KDIM * KDIM];
    for (int i = threadIdx.x; i < KDIM * KDIM; i += blockDim.x) tr[i] = trans[i];
    __syncthreads();

    int gwarp = blockIdx.x * (blockDim.x >> 5) + (threadIdx.x >> 5);
    int lane  = threadIdx.x & 31;
    if (gwarp >= B) return;
    const int b   = gwarp;
    const int len = lengths[b];
    const int*   trow = tags  + (size_t)b * T;
    const float* frow = feats + (size_t)b * T * KDIM;

    float s = 0.0f;
    int carry = START_TAG;
    for (int t0 = 0; t0 < len; t0 += 32) {
        int t = t0 + lane;
        int tg = 0;
        if (t < len) tg = __ldg(trow + t);
        int up   = __shfl_up_sync(FULL, tg, 1);
        int prev = (lane == 0) ? carry : up;
        if (t < len) {
            s += tr[tg * KDIM + prev] + __ldg(frow + t * KDIM + tg);
            if (t == len - 1) s += tr[STOP_TAG * KDIM + tg];
        }
        carry = __shfl_sync(FULL, tg, 31);
    }
#pragma unroll
    for (int k = 16; k; k >>= 1) s += __shfl_xor_sync(FULL, s, k);
    if (lane == 0) g_gold[b] = s;
}

// ---------------------------------------------------------------------------
// Final reduce: mean over B of (fwd - gold)
// ---------------------------------------------------------------------------
__global__ void crf_reduce_kernel(float* __restrict__ out, int B)
{
    __shared__ float sm[32];
    float s = 0.0f;
    for (int i = threadIdx.x; i < B; i += blockDim.x)
        s += g_fwd[i] - g_gold[i];
#pragma unroll
    for (int k = 16; k; k >>= 1) s += __shfl_xor_sync(FULL, s, k);
    int lane = threadIdx.x & 31, w = threadIdx.x >> 5;
    if (lane == 0) sm[w] = s;
    __syncthreads();
    if (threadIdx.x < 32) {
        int nw = blockDim.x >> 5;
        float v = (threadIdx.x < nw) ? sm[threadIdx.x] : 0.0f;
#pragma unroll
        for (int k = 16; k; k >>= 1) v += __shfl_xor_sync(FULL, v, k);
        if (threadIdx.x == 0) out[0] = v / (float)B;
    }
}

extern "C" void kernel_launch(void* const* d_in, const int* in_sizes, int n_in,
                              void* d_out, int out_size)
{
    const float* feats   = (const float*)d_in[0];
    const float* trans   = (const float*)d_in[1];
    const int*   tags    = (const int*)d_in[2];
    const int*   lengths = (const int*)d_in[3];

    int B = in_sizes[3];
    int T = in_sizes[2] / B;

    int wpb = 4;                       // 128 threads = 4 warps per block
    int blocks = (B + wpb - 1) / wpb;  // 256 blocks for B=1024 -> all resident

    crf_fwd_kernel<<<blocks, 128>>>(feats, trans, lengths, B, T);
    crf_gold_kernel<<<blocks, 128>>>(feats, trans, tags, lengths, B, T);
    crf_reduce_kernel<<<1, 256>>>((float*)d_out, B);
}

// round 6
// speedup vs baseline: 2.3667x; 2.3667x over previous
#include <cuda_runtime.h>

#define FULL 0xffffffffu
#define START_TAG 7
#define STOP_TAG 8
#define KDIM 9
#define SEG 8
#define CH 16   // load-ring depth (steps per chunk)

// scratch (device globals: allocation-free rule)
__device__ float g_fwd[2048];
__device__ float g_gold[2048 * SEG];

__device__ __forceinline__ float ex2(float x) {
    float y; asm("ex2.approx.f32 %0, %1;" : "=f"(y) : "f"(x)); return y;
}
__device__ __forceinline__ float lg2(float x) {
    float y; asm("lg2.approx.f32 %0, %1;" : "=f"(y) : "f"(x)); return y;
}
__device__ __forceinline__ float rcpa(float x) {
    float y; asm("rcp.approx.f32 %0, %1;" : "=f"(y) : "f"(x)); return y;
}

// ---------------------------------------------------------------------------
// Forward scan body: one warp per sentence, lanes 0..8 = states.
// Linear domain p = exp2(alpha). Step chain: 1 shfl round + 9-term FMA dot
// + 1 mul (~55-60 cyc). exp2(feat) precomputed off-chain from a 16-deep
// register ring. Renormalize by lane0 every 8 steps (overflow-safe).
// ---------------------------------------------------------------------------
__device__ __forceinline__ void fwd_warp(
    const float* __restrict__ feats, const float* __restrict__ trans,
    const int* __restrict__ lengths, int b, int lane, int T)
{
    const float L2E = 1.4426950408889634f;
    const float LN2 = 0.6931471805599453f;

    const int len = lengths[b];
    const bool act = (lane < KDIM);
    const int  row = act ? lane : 0;

    // E2[j=lane][i] = exp2(trans[j][i]*log2e). Row START -> exactly 0.
    float E2[KDIM];
#pragma unroll
    for (int i = 0; i < KDIM; i++) {
        float tv = __ldg(trans + row * KDIM + i);
        E2[i] = act ? ex2(tv * L2E) : 0.0f;
    }
    const float e2stop = act ? ex2(__ldg(trans + STOP_TAG * KDIM + lane) * L2E) : 0.0f;

    const float* frow = feats + (size_t)b * T * KDIM;

    // static register ring: nf = raw loads in flight, cf = exp2(feat*l2e)
    float nf[CH], cf[CH];
#pragma unroll
    for (int i = 0; i < CH; i++) {
        int tt = (i < T) ? i : (T - 1);
        nf[i] = act ? __ldg(frow + (size_t)tt * KDIM + lane) : 0.0f;
    }
#pragma unroll
    for (int i = 0; i < CH; i++) cf[i] = ex2(nf[i] * L2E);

    float p = (lane == START_TAG) ? 1.0f : 0.0f;
    float C = 0.0f;

#define DOT(OUT)                                                     \
    {   float v0 = __shfl_sync(FULL, p, 0);                          \
        float v1 = __shfl_sync(FULL, p, 1);                          \
        float v2 = __shfl_sync(FULL, p, 2);                          \
        float v3 = __shfl_sync(FULL, p, 3);                          \
        float v4 = __shfl_sync(FULL, p, 4);                          \
        float v5 = __shfl_sync(FULL, p, 5);                          \
        float v6 = __shfl_sync(FULL, p, 6);                          \
        float v7 = __shfl_sync(FULL, p, 7);                          \
        float v8 = __shfl_sync(FULL, p, 8);                          \
        float a0 = fmaf(E2[1], v1, E2[0] * v0);                      \
        float a1 = fmaf(E2[3], v3, E2[2] * v2);                      \
        float a2 = fmaf(E2[5], v5, E2[4] * v4);                      \
        float a3 = fmaf(E2[7], v7, E2[6] * v6);                      \
        OUT = (a0 + a1) + fmaf(E2[8], v8, a2 + a3); }

// normalize by lane0 (always > 0: state0 reachable from START from step 1 on)
#define RENORM                                                       \
    {   float q = __shfl_sync(FULL, p, 0);                           \
        p *= rcpa(q);                                                \
        C += lg2(q); }

    const int nfull = len >> 4;   // full chunks of CH=16, all steps unguarded
    for (int c = 0; c < nfull; c++) {
        // issue next chunk's loads immediately (in flight during the 16 steps)
        int base = (c + 1) << 4;
#pragma unroll
        for (int i = 0; i < CH; i++) {
            int tt = base + i; tt = (tt < T) ? tt : (T - 1);
            nf[i] = act ? __ldg(frow + (size_t)tt * KDIM + lane) : 0.0f;
        }
        // 16 unguarded steps, renorm after 8 and after 16 (overflow safety)
#pragma unroll
        for (int i = 0; i < 8; i++) { float s; DOT(s); p = s * cf[i]; }
        RENORM;
#pragma unroll
        for (int i = 8; i < CH; i++) { float s; DOT(s); p = s * cf[i]; }
        RENORM;
        // convert next chunk (loads have had a full chunk duration to land)
#pragma unroll
        for (int i = 0; i < CH; i++) cf[i] = ex2(nf[i] * L2E);
    }

    // tail: up to 15 guarded steps (renorm mid-way for safety)
    int t0 = nfull << 4;
#pragma unroll
    for (int i = 0; i < 8; i++) {
        float s; DOT(s);
        float pn = s * cf[i];
        p = (t0 + i < len) ? pn : p;
    }
    RENORM;
#pragma unroll
    for (int i = 8; i < CH - 1; i++) {
        float s; DOT(s);
        float pn = s * cf[i];
        p = (t0 + i < len) ? pn : p;
    }
#undef DOT
#undef RENORM

    // logZ = ln2 * (C + log2 sum_j p_j * exp2(trans[STOP,j]*l2e))
    float v = p * e2stop;            // lanes >= 9: p == 0
    float sum = v;
#pragma unroll
    for (int k = 8; k; k >>= 1)
        sum += __shfl_xor_sync(FULL, sum, k, 16);
    if (lane == 0)
        g_fwd[b] = LN2 * (C + lg2(sum));
}

// ---------------------------------------------------------------------------
// Gold-path segment body: one warp covers one T/SEG slice of one sentence.
// ---------------------------------------------------------------------------
__device__ __forceinline__ void gold_warp(
    const float* __restrict__ feats, const float* __restrict__ trans,
    const int* __restrict__ tags, const int* __restrict__ lengths,
    const float* tr, int gw, int lane, int T)
{
    const int b   = gw / SEG;
    const int seg = gw - b * SEG;
    const int len = lengths[b];
    const int slen = (T + SEG - 1) / SEG;
    const int t_begin = seg * slen;
    const int t_end   = (t_begin + slen < len) ? (t_begin + slen) : len;

    float s = 0.0f;
    if (t_begin < t_end) {
        const int*   trow = tags  + (size_t)b * T;
        const float* frow = feats + (size_t)b * T * KDIM;
        int carry = (t_begin == 0) ? START_TAG : __ldg(trow + t_begin - 1);
        for (int tt = t_begin; tt < t_end; tt += 32) {
            int t  = tt + lane;
            int tg = (t < t_end) ? __ldg(trow + t) : 0;
            int up = __shfl_up_sync(FULL, tg, 1);
            int prev = (lane == 0) ? carry : up;
            if (t < t_end) {
                s += tr[tg * KDIM + prev] + __ldg(frow + (size_t)t * KDIM + tg);
                if (t == len - 1) s += tr[STOP_TAG * KDIM + tg];
            }
            carry = __shfl_sync(FULL, tg, 31);
        }
    }
#pragma unroll
    for (int k = 16; k; k >>= 1) s += __shfl_xor_sync(FULL, s, k);
    if (lane == 0) g_gold[gw] = s;
}

// ---------------------------------------------------------------------------
// Fused kernel: blocks [0, fwdBlocks) run the forward scan (scheduled first,
// they are the long pole); the rest run gold segments, overlapping with fwd.
// ---------------------------------------------------------------------------
__global__ void __launch_bounds__(128) crf_main_kernel(
    const float* __restrict__ feats, const float* __restrict__ trans,
    const int* __restrict__ tags, const int* __restrict__ lengths,
    int B, int T, int fwdBlocks)
{
    __shared__ float tr[KDIM * KDIM];
    for (int i = threadIdx.x; i < KDIM * KDIM; i += blockDim.x)
        tr[i] = trans[i];
    __syncthreads();

    int warpInBlk = threadIdx.x >> 5;
    int lane      = threadIdx.x & 31;

    if (blockIdx.x < fwdBlocks) {
        int b = blockIdx.x * 4 + warpInBlk;
        if (b < B) fwd_warp(feats, trans, lengths, b, lane, T);
    } else {
        int gw = (blockIdx.x - fwdBlocks) * 4 + warpInBlk;
        if (gw < B * SEG) gold_warp(feats, trans, tags, lengths, tr, gw, lane, T);
    }
}

// ---------------------------------------------------------------------------
// Final reduce: mean over B of (fwd - sum of gold partials)
// ---------------------------------------------------------------------------
__global__ void crf_reduce_kernel(float* __restrict__ out, int B)
{
    __shared__ float sm[32];
    float s = 0.0f;
    for (int i = threadIdx.x; i < B * SEG; i += blockDim.x) {
        s -= g_gold[i];
        if (i < B) s += g_fwd[i];
    }
#pragma unroll
    for (int k = 16; k; k >>= 1) s += __shfl_xor_sync(FULL, s, k);
    int lane = threadIdx.x & 31, w = threadIdx.x >> 5;
    if (lane == 0) sm[w] = s;
    __syncthreads();
    if (threadIdx.x < 32) {
        int nw = blockDim.x >> 5;
        float v = (threadIdx.x < nw) ? sm[threadIdx.x] : 0.0f;
#pragma unroll
        for (int k = 16; k; k >>= 1) v += __shfl_xor_sync(FULL, v, k);
        if (threadIdx.x == 0) out[0] = v / (float)B;
    }
}

extern "C" void kernel_launch(void* const* d_in, const int* in_sizes, int n_in,
                              void* d_out, int out_size)
{
    const float* feats   = (const float*)d_in[0];
    const float* trans   = (const float*)d_in[1];
    const int*   tags    = (const int*)d_in[2];
    const int*   lengths = (const int*)d_in[3];

    int B = in_sizes[3];
    int T = in_sizes[2] / B;

    int fwdBlocks  = (B + 3) / 4;               // 4 warps / block
    int goldBlocks = (B * SEG + 3) / 4;

    crf_main_kernel<<<fwdBlocks + goldBlocks, 128>>>(
        feats, trans, tags, lengths, B, T, fwdBlocks);
    crf_reduce_kernel<<<1, 256>>>((float*)d_out, B);
}